// round 6
// baseline (speedup 1.0000x reference)
#include <cuda_runtime.h>
#include <math.h>

#define NB 64
#define TT 512
#define DD 1024
#define HH 1024

// Scratch for xh = x@W_xh + b_xh + b_hh (128 MB, module-load alloc: allowed)
static __device__ float g_xh[(size_t)NB * TT * HH];

// ---------------------------------------------------------------------------
// Kernel A: xh = x @ W_xh + (b_xh + b_hh)
// fp32 SGEMM: BM=BN=128, BK=8, 256 threads, 8x8 microtile.
// ---------------------------------------------------------------------------
__global__ __launch_bounds__(256, 2)
void gemm_xh_kernel(const float* __restrict__ A, const float* __restrict__ B,
                    const float* __restrict__ bxh, const float* __restrict__ bhh)
{
    __shared__ float As[8][128];
    __shared__ float Bs[8][128];

    const int tid = threadIdx.x;
    const int bm = blockIdx.y * 128;
    const int bn = blockIdx.x * 128;
    const int tx = tid & 15;
    const int ty = tid >> 4;

    const int a_row = tid >> 1;
    const int a_col = (tid & 1) << 2;
    const int b_row = tid >> 5;
    const int b_col = (tid & 31) << 2;

    const float* Aptr = A + (size_t)(bm + a_row) * DD + a_col;
    const float* Bptr = B + (size_t)b_row * HH + bn + b_col;

    float acc[8][8];
#pragma unroll
    for (int i = 0; i < 8; ++i)
#pragma unroll
        for (int j = 0; j < 8; ++j) acc[i][j] = 0.0f;

    for (int k0 = 0; k0 < DD; k0 += 8) {
        float4 av = *(const float4*)(Aptr + k0);
        float4 bv = *(const float4*)(Bptr + (size_t)k0 * HH);
        As[a_col + 0][a_row] = av.x;
        As[a_col + 1][a_row] = av.y;
        As[a_col + 2][a_row] = av.z;
        As[a_col + 3][a_row] = av.w;
        *(float4*)&Bs[b_row][b_col] = bv;
        __syncthreads();

#pragma unroll
        for (int k = 0; k < 8; ++k) {
            float a_frag[8], b_frag[8];
            *(float4*)&a_frag[0] = *(const float4*)&As[k][ty * 8];
            *(float4*)&a_frag[4] = *(const float4*)&As[k][ty * 8 + 4];
            *(float4*)&b_frag[0] = *(const float4*)&Bs[k][tx * 8];
            *(float4*)&b_frag[4] = *(const float4*)&Bs[k][tx * 8 + 4];
#pragma unroll
            for (int i = 0; i < 8; ++i)
#pragma unroll
                for (int j = 0; j < 8; ++j)
                    acc[i][j] = fmaf(a_frag[i], b_frag[j], acc[i][j]);
        }
        __syncthreads();
    }

    float bsum[8];
#pragma unroll
    for (int j = 0; j < 8; ++j) {
        int col = bn + tx * 8 + j;
        bsum[j] = bxh[col] + bhh[col];
    }
#pragma unroll
    for (int i = 0; i < 8; ++i) {
        float* Crow = g_xh + (size_t)(bm + ty * 8 + i) * HH + bn + tx * 8;
        float4 o0, o1;
        o0.x = acc[i][0] + bsum[0]; o0.y = acc[i][1] + bsum[1];
        o0.z = acc[i][2] + bsum[2]; o0.w = acc[i][3] + bsum[3];
        o1.x = acc[i][4] + bsum[4]; o1.y = acc[i][5] + bsum[5];
        o1.z = acc[i][6] + bsum[6]; o1.w = acc[i][7] + bsum[7];
        *(float4*)(Crow + 0) = o0;
        *(float4*)(Crow + 4) = o1;
    }
}

// ---------------------------------------------------------------------------
// Kernel B: one recurrence step.  y[:,t,:] = tanh(xh[:,t,:] + y[:,t-1,:]@Whh)
//
// 128 CTAs x 512 threads (16 warps). CTA owns 8 cols [8b, 8b+8).
// Warp (cg = wid&3, rg = wid>>2) fully owns:
//   cols {c0+2cg, c0+2cg+1} x rows {r : r % 4 == rg}  x  ALL k (0..1023).
// Lane k-slice: k = 128*i + 4*lane + kk  (i<8, kk<4)  -> w[8][4][2] = 64 regs.
// Per row: 8x LDS.128 (all-distinct, conflict-free quarters) + 64 FMA,
// then a 5-level butterfly gives the full-k sums; lanes 0/1 fuse xh + tanh
// and store. NO cross-warp reduction, NO accs smem.
// h_{t-1} staged in 8-row chunks (32 KB smem) with register prefetch.
// ---------------------------------------------------------------------------
__global__ __launch_bounds__(512, 1)
void rnn_step_kernel(float* __restrict__ y, const float* __restrict__ Whh, int t)
{
    __shared__ float hs[8][1024];   // 32 KB, one 8-row chunk of h_{t-1}

    const int tid = threadIdx.x;
    const int lane = tid & 31;
    const int wid = tid >> 5;           // 0..15
    const int cg = wid & 3;             // col-pair index
    const int rg = wid >> 2;            // row residue (mod 4)
    const int c0 = blockIdx.x * 8;
    const int cA = c0 + 2 * cg;         // this warp's two columns: cA, cA+1
    const size_t nstride = (size_t)TT * HH;

    if (t == 0) {
        // h_prev = 0: y0 = tanh(xh0). One output per thread.
        int row = tid >> 3;
        int cc = c0 + (tid & 7);
        size_t off = (size_t)row * nstride + cc;
        y[off] = tanhf(g_xh[off]);
        return;
    }

    // ---- W_hh slice into registers: w[i][kk][j] = Whh[128i+4lane+kk][cA+j] ----
    float w0[8][4], w1[8][4];
#pragma unroll
    for (int i = 0; i < 8; ++i) {
#pragma unroll
        for (int kk = 0; kk < 4; ++kk) {
            const float* wp = Whh + (size_t)(128 * i + 4 * lane + kk) * HH + cA;
            w0[i][kk] = wp[0];
            w1[i][kk] = wp[1];
        }
    }

    const float* hprev = y + (size_t)(t - 1) * HH;   // + n*nstride per row
    const int srow = tid >> 6;          // 0..7 staging row within chunk
    const int seg  = tid & 63;          // 64 threads per row

    // ---- stage chunk 0 (rows 0..7) ----
#pragma unroll
    for (int i = 0; i < 4; ++i) {
        float4 v = *(const float4*)(hprev + (size_t)srow * nstride + 4 * seg + 256 * i);
        *(float4*)&hs[srow][4 * seg + 256 * i] = v;
    }
    __syncthreads();

    for (int ch = 0; ch < 8; ++ch) {
        // prefetch next chunk into registers (LDG latency overlapped w/ compute)
        float4 pf[4];
        if (ch < 7) {
            const float* src = hprev + (size_t)(((ch + 1) << 3) + srow) * nstride;
#pragma unroll
            for (int i = 0; i < 4; ++i)
                pf[i] = *(const float4*)(src + 4 * seg + 256 * i);
        }

        // ---- compute this warp's 2 rows of the chunk: local rows rg, rg+4 ----
#pragma unroll
        for (int rr = 0; rr < 2; ++rr) {
            const int rl = rg + 4 * rr;          // 0..7 within chunk
            const int row = (ch << 3) + rl;      // global row 0..63

            // early xh load for the two storing lanes (latency hidden by FMAs)
            float xv = 0.0f;
            size_t off = 0;
            if (lane < 2) {
                off = (size_t)row * nstride + (size_t)t * HH + (cA + lane);
                xv = g_xh[off];
            }

            const float* hrow = &hs[rl][4 * lane];
            float a0 = 0.f, a1 = 0.f, b0 = 0.f, b1 = 0.f;  // 2 chains per col
#pragma unroll
            for (int i = 0; i < 8; ++i) {
                float4 h = *(const float4*)(hrow + 128 * i);
                if (i & 1) {
                    a1 = fmaf(h.x, w0[i][0], a1); b1 = fmaf(h.x, w1[i][0], b1);
                    a1 = fmaf(h.y, w0[i][1], a1); b1 = fmaf(h.y, w1[i][1], b1);
                    a1 = fmaf(h.z, w0[i][2], a1); b1 = fmaf(h.z, w1[i][2], b1);
                    a1 = fmaf(h.w, w0[i][3], a1); b1 = fmaf(h.w, w1[i][3], b1);
                } else {
                    a0 = fmaf(h.x, w0[i][0], a0); b0 = fmaf(h.x, w1[i][0], b0);
                    a0 = fmaf(h.y, w0[i][1], a0); b0 = fmaf(h.y, w1[i][1], b0);
                    a0 = fmaf(h.z, w0[i][2], a0); b0 = fmaf(h.z, w1[i][2], b0);
                    a0 = fmaf(h.w, w0[i][3], a0); b0 = fmaf(h.w, w1[i][3], b0);
                }
            }
            float pA = a0 + a1;   // col cA partial (this lane's 32 k)
            float pB = b0 + b1;   // col cA+1 partial

            // full-warp butterfly: sum over all 32 lanes (k = 0..1023)
#pragma unroll
            for (int m = 16; m >= 1; m >>= 1) {
                pA += __shfl_xor_sync(0xffffffffu, pA, m);
                pB += __shfl_xor_sync(0xffffffffu, pB, m);
            }

            if (lane < 2) {
                float s = (lane == 0) ? pA : pB;
                y[off] = tanhf(xv + s);
            }
        }

        __syncthreads();   // all hs reads done before overwrite
        if (ch < 7) {
#pragma unroll
            for (int i = 0; i < 4; ++i)
                *(float4*)&hs[srow][4 * seg + 256 * i] = pf[i];
        }
        __syncthreads();   // next chunk visible
    }
}

// ---------------------------------------------------------------------------
// Launch. Inputs: x, weight_xh, weight_hh, bias_xh, bias_hh.
// Pure kernel launches — graph-capturable, no device state, static smem only.
// ---------------------------------------------------------------------------
extern "C" void kernel_launch(void* const* d_in, const int* in_sizes, int n_in,
                              void* d_out, int out_size)
{
    const float* x   = (const float*)d_in[0];
    const float* wxh = (const float*)d_in[1];
    const float* whh = (const float*)d_in[2];
    const float* bxh = (const float*)d_in[3];
    const float* bhh = (const float*)d_in[4];
    float* y = (float*)d_out;

    (void)in_sizes; (void)n_in; (void)out_size;

    dim3 g1(HH / 128, (NB * TT) / 128);   // (8, 256)
    gemm_xh_kernel<<<g1, 256>>>(x, wxh, bxh, bhh);

    for (int t = 0; t < TT; ++t)
        rnn_step_kernel<<<128, 512>>>(y, whh, t);
}

// round 9
// speedup vs baseline: 2.7100x; 2.7100x over previous
#include <cuda_runtime.h>
#include <cuda_bf16.h>
#include <math.h>

#define NB 64
#define TT 512
#define DD 1024
#define HH 1024

// Round 8 resubmission of the bf16-split tensor-core recurrence.
// (Source perturbed vs prior round; semantics identical except
//  __halves2bfloat162 replaces the __nv_bfloat162 constructor.)

// xh = x@W_xh + b_xh + b_hh scratch (fp32)
static __device__ float g_xh[(size_t)NB * TT * HH];

// Fragment-ready split-W:  g_wb16[comp][nc][s][lane][8]  (comp: 0=hi, 1=lo)
//   elem e8 = j*4 + breg*2 + e ; k = 16s + 2*t4 + 8*breg + e ; n = 16nc + 8j + g
static __device__ __nv_bfloat16 g_wb16[2u * 64 * 64 * 32 * 8];     // 2 x 1M elems

// Fragment-ready split-H ping-pong: g_ha16[pp][comp][mt][s][lane][8]
//   elem e8 = areg*2 + e ; row = 16mt + g + 8*(areg&1) ; k = 16s + 2*t4 + 8*(areg>>1) + e
static __device__ __nv_bfloat16 g_ha16[2u * 2 * 4 * 64 * 32 * 8];  // 256K elems

#define WB_LO_OFF 1048576u   // g_wb16 lo-component offset (elements)
#define HA_PP_OFF 131072u    // g_ha16 parity stride (elements)
#define HA_LO_OFF 65536u     // g_ha16 lo-component offset (elements)

// ---------------------------------------------------------------------------
// mma.sync m16n8k16 row.col f32 += bf16*bf16
// ---------------------------------------------------------------------------
__device__ __forceinline__ void mma_bf16(float4& d, const uint4& a,
                                         unsigned b0, unsigned b1)
{
    asm volatile(
        "mma.sync.aligned.m16n8k16.row.col.f32.bf16.bf16.f32 "
        "{%0,%1,%2,%3}, {%4,%5,%6,%7}, {%8,%9}, {%0,%1,%2,%3};\n"
        : "+f"(d.x), "+f"(d.y), "+f"(d.z), "+f"(d.w)
        : "r"(a.x), "r"(a.y), "r"(a.z), "r"(a.w), "r"(b0), "r"(b1));
}

// ---------------------------------------------------------------------------
// Precompute: split W_hh into fragment-ready hi/lo bf16. One thread per elem.
// ---------------------------------------------------------------------------
__global__ void split_w_kernel(const float* __restrict__ Whh)
{
    const unsigned idx = blockIdx.x * 256u + threadIdx.x;   // 0 .. 2^20-1
    if (idx >= 64u * 64u * 32u * 8u) return;
    const unsigned e8   = idx & 7u;
    const unsigned lane = (idx >> 3) & 31u;
    const unsigned s    = (idx >> 8) & 63u;
    const unsigned nc   = idx >> 14;
    const unsigned g = lane >> 2, t4 = lane & 3u;
    const unsigned j = e8 >> 2, breg = (e8 >> 1) & 1u, e = e8 & 1u;
    const unsigned k = 16u * s + 2u * t4 + 8u * breg + e;
    const unsigned n = 16u * nc + 8u * j + g;
    const float v = Whh[(size_t)k * HH + n];
    const __nv_bfloat16 hi = __float2bfloat16(v);
    const __nv_bfloat16 lo = __float2bfloat16(v - __bfloat162float(hi));
    g_wb16[idx] = hi;
    g_wb16[idx + WB_LO_OFF] = lo;
}

// ---------------------------------------------------------------------------
// Epilogue helper: write an h pair (cols cp, cp+1 of CTA nc, row r) to y and
// to the fragment-ready split buffer for step t (parity t&1).
// ---------------------------------------------------------------------------
__device__ __forceinline__ void write_h_pair(float h0, float h1, int r, int cp,
                                             int nc, int t, float* __restrict__ y)
{
    const size_t nstride = (size_t)TT * HH;
    *(float2*)&y[(size_t)r * nstride + (size_t)t * HH + 16 * nc + cp] =
        make_float2(h0, h1);

    const int mt = r >> 4, rr = r & 15;
    const int g = rr & 7, t4 = (cp >> 1) & 3;
    const int lane = g * 4 + t4;
    const int areg = ((rr >> 3) & 1) + ((cp >> 3) << 1);
    const size_t base = (size_t)(t & 1) * HA_PP_OFF + (size_t)mt * 16384
                      + (size_t)nc * 256 + lane * 8 + areg * 2;
    const __nv_bfloat16 hi0 = __float2bfloat16(h0);
    const __nv_bfloat16 hi1 = __float2bfloat16(h1);
    const __nv_bfloat16 lo0 = __float2bfloat16(h0 - __bfloat162float(hi0));
    const __nv_bfloat16 lo1 = __float2bfloat16(h1 - __bfloat162float(hi1));
    *(__nv_bfloat162*)&g_ha16[base]             = __halves2bfloat162(hi0, hi1);
    *(__nv_bfloat162*)&g_ha16[base + HA_LO_OFF] = __halves2bfloat162(lo0, lo1);
}

// ---------------------------------------------------------------------------
// t = 0:  h0 = tanh(xh0).  64 CTAs x 512 threads; thread -> (row, col-pair).
// ---------------------------------------------------------------------------
__global__ __launch_bounds__(512)
void rnn_step0_kernel(float* __restrict__ y)
{
    const int tid = threadIdx.x;
    const int nc = blockIdx.x;
    const int r = tid >> 3;
    const int cp = (tid & 7) << 1;
    const size_t nstride = (size_t)TT * HH;
    const float2 xh = *(const float2*)&g_xh[(size_t)r * nstride + 16 * nc + cp];
    write_h_pair(tanhf(xh.x), tanhf(xh.y), r, cp, nc, 0, y);
}

// ---------------------------------------------------------------------------
// t >= 1:  h_t = tanh(xh_t + h_{t-1} @ W_hh) via 3-term bf16-split mma.sync.
// 64 CTAs (16 cols each) x 512 threads (16 warps = 4 mtiles x 4 kgroups).
// Warp mainloop: 16 ksteps x (4 coalesced LDG.128 + 6 HMMA), D in registers.
// Then 16 KB smem k-reduction + fused epilogue.
// ---------------------------------------------------------------------------
__global__ __launch_bounds__(512)
void rnn_step_kernel(float* __restrict__ y, int t)
{
    __shared__ float redD[4 * 4 * 16 * 16];   // [mt][ksub][rr][cc], 16 KB

    const int tid = threadIdx.x;
    const int lane = tid & 31;
    const int wid = tid >> 5;
    const int mt = wid & 3;
    const int ksub = wid >> 2;
    const int nc = blockIdx.x;

    // A (prev h) fragments, parity (t-1)&1
    const size_t haoff = (size_t)((t - 1) & 1) * HA_PP_OFF + (size_t)mt * 16384
                       + (size_t)(ksub * 16) * 256 + lane * 8;
    const __nv_bfloat16* pahi = g_ha16 + haoff;
    const __nv_bfloat16* palo = pahi + HA_LO_OFF;
    // B (W) fragments
    const size_t wboff = ((size_t)nc * 64 + ksub * 16) * 256 + lane * 8;
    const __nv_bfloat16* pbhi = g_wb16 + wboff;
    const __nv_bfloat16* pblo = pbhi + WB_LO_OFF;

    float4 d0 = make_float4(0.f, 0.f, 0.f, 0.f);   // cols 0-7 of this nc tile
    float4 d1 = make_float4(0.f, 0.f, 0.f, 0.f);   // cols 8-15

#pragma unroll 4
    for (int ss = 0; ss < 16; ++ss) {
        const uint4 ahi = *(const uint4*)(pahi + ss * 256);
        const uint4 alo = *(const uint4*)(palo + ss * 256);
        const uint4 bhi = *(const uint4*)(pbhi + ss * 256);
        const uint4 blo = *(const uint4*)(pblo + ss * 256);
        mma_bf16(d0, ahi, bhi.x, bhi.y);
        mma_bf16(d1, ahi, bhi.z, bhi.w);
        mma_bf16(d0, ahi, blo.x, blo.y);
        mma_bf16(d1, ahi, blo.z, blo.w);
        mma_bf16(d0, alo, bhi.x, bhi.y);
        mma_bf16(d1, alo, bhi.z, bhi.w);
    }

    // store D fragments: rows g, g+8 ; cols 2*t4 (+1) within each 8-col tile
    {
        const int g = lane >> 2, t4 = lane & 3;
        float* rd = redD + (mt * 4 + ksub) * 256;
        *(float2*)&rd[g * 16 + 2 * t4]           = make_float2(d0.x, d0.y);
        *(float2*)&rd[(g + 8) * 16 + 2 * t4]     = make_float2(d0.z, d0.w);
        *(float2*)&rd[g * 16 + 8 + 2 * t4]       = make_float2(d1.x, d1.y);
        *(float2*)&rd[(g + 8) * 16 + 8 + 2 * t4] = make_float2(d1.z, d1.w);
    }
    __syncthreads();

    // reduce 4 kgroups + xh + tanh + store (thread -> row r, col pair cp)
    {
        const int r = tid >> 3;
        const int cp = (tid & 7) << 1;
        const int mt2 = r >> 4, rr = r & 15;
        const float* rp = redD + (mt2 * 4) * 256 + rr * 16 + cp;
        const float sx = rp[0] + rp[256] + rp[512] + rp[768];
        const float sy = rp[1] + rp[257] + rp[513] + rp[769];
        const size_t nstride = (size_t)TT * HH;
        const float2 xh = *(const float2*)&g_xh[(size_t)r * nstride
                                                + (size_t)t * HH + 16 * nc + cp];
        write_h_pair(tanhf(xh.x + sx), tanhf(xh.y + sy), r, cp, nc, t, y);
    }
}

// ---------------------------------------------------------------------------
// Kernel A: xh = x @ W_xh + (b_xh + b_hh).  fp32 SGEMM (proven correct).
// ---------------------------------------------------------------------------
__global__ __launch_bounds__(256, 2)
void gemm_xh_kernel(const float* __restrict__ A, const float* __restrict__ B,
                    const float* __restrict__ bxh, const float* __restrict__ bhh)
{
    __shared__ float As[8][128];
    __shared__ float Bs[8][128];

    const int tid = threadIdx.x;
    const int bm = blockIdx.y * 128;
    const int bn = blockIdx.x * 128;
    const int tx = tid & 15;
    const int ty = tid >> 4;

    const int a_row = tid >> 1;
    const int a_col = (tid & 1) << 2;
    const int b_row = tid >> 5;
    const int b_col = (tid & 31) << 2;

    const float* Aptr = A + (size_t)(bm + a_row) * DD + a_col;
    const float* Bptr = B + (size_t)b_row * HH + bn + b_col;

    float acc[8][8];
#pragma unroll
    for (int i = 0; i < 8; ++i)
#pragma unroll
        for (int j = 0; j < 8; ++j) acc[i][j] = 0.0f;

    for (int k0 = 0; k0 < DD; k0 += 8) {
        const float4 av = *(const float4*)(Aptr + k0);
        const float4 bv = *(const float4*)(Bptr + (size_t)k0 * HH);
        As[a_col + 0][a_row] = av.x;
        As[a_col + 1][a_row] = av.y;
        As[a_col + 2][a_row] = av.z;
        As[a_col + 3][a_row] = av.w;
        *(float4*)&Bs[b_row][b_col] = bv;
        __syncthreads();

#pragma unroll
        for (int k = 0; k < 8; ++k) {
            float a_frag[8], b_frag[8];
            *(float4*)&a_frag[0] = *(const float4*)&As[k][ty * 8];
            *(float4*)&a_frag[4] = *(const float4*)&As[k][ty * 8 + 4];
            *(float4*)&b_frag[0] = *(const float4*)&Bs[k][tx * 8];
            *(float4*)&b_frag[4] = *(const float4*)&Bs[k][tx * 8 + 4];
#pragma unroll
            for (int i = 0; i < 8; ++i)
#pragma unroll
                for (int j = 0; j < 8; ++j)
                    acc[i][j] = fmaf(a_frag[i], b_frag[j], acc[i][j]);
        }
        __syncthreads();
    }

    float bsum[8];
#pragma unroll
    for (int j = 0; j < 8; ++j) {
        const int col = bn + tx * 8 + j;
        bsum[j] = bxh[col] + bhh[col];
    }
#pragma unroll
    for (int i = 0; i < 8; ++i) {
        float* Crow = g_xh + (size_t)(bm + ty * 8 + i) * HH + bn + tx * 8;
        float4 o0, o1;
        o0.x = acc[i][0] + bsum[0]; o0.y = acc[i][1] + bsum[1];
        o0.z = acc[i][2] + bsum[2]; o0.w = acc[i][3] + bsum[3];
        o1.x = acc[i][4] + bsum[4]; o1.y = acc[i][5] + bsum[5];
        o1.z = acc[i][6] + bsum[6]; o1.w = acc[i][7] + bsum[7];
        *(float4*)(Crow + 0) = o0;
        *(float4*)(Crow + 4) = o1;
    }
}

// ---------------------------------------------------------------------------
// Launch. Inputs: x, weight_xh, weight_hh, bias_xh, bias_hh.
// Pure kernel launches, static smem only — graph-capturable.
// ---------------------------------------------------------------------------
extern "C" void kernel_launch(void* const* d_in, const int* in_sizes, int n_in,
                              void* d_out, int out_size)
{
    const float* x   = (const float*)d_in[0];
    const float* wxh = (const float*)d_in[1];
    const float* whh = (const float*)d_in[2];
    const float* bxh = (const float*)d_in[3];
    const float* bhh = (const float*)d_in[4];
    float* y = (float*)d_out;

    (void)in_sizes; (void)n_in; (void)out_size;

    split_w_kernel<<<4096, 256>>>(whh);

    dim3 g1(HH / 128, (NB * TT) / 128);   // (8, 256)
    gemm_xh_kernel<<<g1, 256>>>(x, wxh, bxh, bhh);

    rnn_step0_kernel<<<64, 512>>>(y);
    for (int t = 1; t < TT; ++t)
        rnn_step_kernel<<<64, 512>>>(y, t);
}

// round 10
// speedup vs baseline: 3.2652x; 1.2049x over previous
#include <cuda_runtime.h>
#include <cuda_bf16.h>
#include <math.h>

#define NB 64
#define TT 512
#define DD 1024
#define HH 1024

// xh = x@W_xh + b_xh + b_hh scratch (fp32)
static __device__ float g_xh[(size_t)NB * TT * HH];

// Fragment-ready split-W:  g_wb16[comp][nc][s][lane][8]  (comp: 0=hi, 1=lo)
static __device__ __nv_bfloat16 g_wb16[2u * 64 * 64 * 32 * 8];     // 2 x 1M elems

// Fragment-ready split-H ping-pong: g_ha16[pp][comp][mt][s][lane][8]
//   mt = row>>4  — group g's rows are exactly the mt = g slice.
static __device__ __nv_bfloat16 g_ha16[2u * 2 * 4 * 64 * 32 * 8];  // 512K elems

#define WB_LO_OFF 1048576u
#define HA_PP_OFF 131072u
#define HA_LO_OFF 65536u

// ---------------------------------------------------------------------------
// mma.sync m16n8k16 row.col f32 += bf16*bf16
// ---------------------------------------------------------------------------
__device__ __forceinline__ void mma_bf16(float4& d, const uint4& a,
                                         unsigned b0, unsigned b1)
{
    asm volatile(
        "mma.sync.aligned.m16n8k16.row.col.f32.bf16.bf16.f32 "
        "{%0,%1,%2,%3}, {%4,%5,%6,%7}, {%8,%9}, {%0,%1,%2,%3};\n"
        : "+f"(d.x), "+f"(d.y), "+f"(d.z), "+f"(d.w)
        : "r"(a.x), "r"(a.y), "r"(a.z), "r"(a.w), "r"(b0), "r"(b1));
}

// ---------------------------------------------------------------------------
// Split W_hh into fragment-ready hi/lo bf16 (one thread per element).
// ---------------------------------------------------------------------------
__global__ void split_w_kernel(const float* __restrict__ Whh)
{
    const unsigned idx = blockIdx.x * 256u + threadIdx.x;
    if (idx >= 64u * 64u * 32u * 8u) return;
    const unsigned e8   = idx & 7u;
    const unsigned lane = (idx >> 3) & 31u;
    const unsigned s    = (idx >> 8) & 63u;
    const unsigned nc   = idx >> 14;
    const unsigned g = lane >> 2, t4 = lane & 3u;
    const unsigned j = e8 >> 2, breg = (e8 >> 1) & 1u, e = e8 & 1u;
    const unsigned k = 16u * s + 2u * t4 + 8u * breg + e;
    const unsigned n = 16u * nc + 8u * j + g;
    const float v = Whh[(size_t)k * HH + n];
    const __nv_bfloat16 hi = __float2bfloat16(v);
    const __nv_bfloat16 lo = __float2bfloat16(v - __bfloat162float(hi));
    g_wb16[idx] = hi;
    g_wb16[idx + WB_LO_OFF] = lo;
}

// ---------------------------------------------------------------------------
// Write h pair (row r, cols 16*nc+cp, +1) to y and the fragment buffer (par t&1)
// ---------------------------------------------------------------------------
__device__ __forceinline__ void write_h_pair(float h0, float h1, int r, int cp,
                                             int nc, int t, float* __restrict__ y)
{
    const size_t nstride = (size_t)TT * HH;
    *(float2*)&y[(size_t)r * nstride + (size_t)t * HH + 16 * nc + cp] =
        make_float2(h0, h1);

    const int mt = r >> 4, rr = r & 15;
    const int g = rr & 7, t4 = (cp >> 1) & 3;
    const int lane = g * 4 + t4;
    const int areg = ((rr >> 3) & 1) + ((cp >> 3) << 1);
    const size_t base = (size_t)(t & 1) * HA_PP_OFF + (size_t)mt * 16384
                      + (size_t)nc * 256 + lane * 8 + areg * 2;
    const __nv_bfloat16 hi0 = __float2bfloat16(h0);
    const __nv_bfloat16 hi1 = __float2bfloat16(h1);
    const __nv_bfloat16 lo0 = __float2bfloat16(h0 - __bfloat162float(hi0));
    const __nv_bfloat16 lo1 = __float2bfloat16(h1 - __bfloat162float(hi1));
    *(__nv_bfloat162*)&g_ha16[base]             = __halves2bfloat162(hi0, hi1);
    *(__nv_bfloat162*)&g_ha16[base + HA_LO_OFF] = __halves2bfloat162(lo0, lo1);
}

// ---------------------------------------------------------------------------
// Persistent cluster recurrence.
// Grid = 32 CTAs = 4 independent clusters of 8 (batch rows are independent:
// group gidx owns rows [16g, 16g+16); groups never communicate).
// CTA (rank in cluster) owns cols [128*rank, 128*rank+128).
// Warp (colg = wid&3, ksub = wid>>2): 32 cols (2 nc tiles) x 256 k (16 ss).
// Per step: prefetch xh -> mainloop (96 LDG.128 + 192 MMA per warp) ->
// redD k-reduction (32 KB) -> fused tanh + dual-format h write ->
// threadfence + HW cluster barrier. No kernel boundaries, no L1 flushes.
// ---------------------------------------------------------------------------
__global__ __cluster_dims__(8, 1, 1) __launch_bounds__(512, 1)
void rnn_persistent_cluster(float* __restrict__ y)
{
    __shared__ float redD[4][16][128];   // [ksub][row][col]  32 KB

    const int tid = threadIdx.x;
    const int lane = tid & 31;
    const int wid = tid >> 5;
    const int colg = wid & 3;
    const int ksub = wid >> 2;
    const int gidx = blockIdx.x >> 3;      // group (row block) 0..3
    const int rank = blockIdx.x & 7;       // cluster CTA rank  0..7
    const size_t nstride = (size_t)TT * HH;

    // Thread's two epilogue pairs: p = tid + 512*v ->
    //   rr = p>>6 (row in group), c = (p&63)*2 (col in CTA's 128)
    int rr_v[2], c_v[2];
#pragma unroll
    for (int v = 0; v < 2; ++v) {
        const int p = tid + 512 * v;
        rr_v[v] = p >> 6;
        c_v[v] = (p & 63) * 2;
    }

    // ---- t = 0 : h0 = tanh(xh0) ----
#pragma unroll
    for (int v = 0; v < 2; ++v) {
        const int r = 16 * gidx + rr_v[v];
        const int c = c_v[v];
        const float2 xh = *(const float2*)&g_xh[(size_t)r * nstride
                                                + 128 * rank + c];
        write_h_pair(tanhf(xh.x), tanhf(xh.y), r, c & 15,
                     8 * rank + (c >> 4), 0, y);
    }
    __threadfence();
    asm volatile("barrier.cluster.arrive.aligned;\n" ::: "memory");
    asm volatile("barrier.cluster.wait.aligned;\n" ::: "memory");

    // B fragment base pointers for this warp's two nc tiles
    const int nc0 = 8 * rank + 2 * colg;
    const __nv_bfloat16* pb0 = g_wb16 + ((size_t)nc0 * 64 + ksub * 16) * 256 + lane * 8;
    const __nv_bfloat16* pb1 = pb0 + 64 * 256;    // nc0+1
    const size_t pa_base = (size_t)gidx * 16384 + (size_t)(ksub * 16) * 256 + lane * 8;

    for (int t = 1; t < TT; ++t) {
        // prefetch xh for this thread's epilogue pairs (hides DRAM latency)
        float2 xh_pre[2];
#pragma unroll
        for (int v = 0; v < 2; ++v) {
            const int r = 16 * gidx + rr_v[v];
            xh_pre[v] = *(const float2*)&g_xh[(size_t)r * nstride
                                              + (size_t)t * HH + 128 * rank + c_v[v]];
        }

        // A fragments for parity (t-1)&1
        const __nv_bfloat16* pa = g_ha16 + (size_t)((t - 1) & 1) * HA_PP_OFF + pa_base;

        float4 d00 = make_float4(0.f,0.f,0.f,0.f), d01 = make_float4(0.f,0.f,0.f,0.f);
        float4 d10 = make_float4(0.f,0.f,0.f,0.f), d11 = make_float4(0.f,0.f,0.f,0.f);

#pragma unroll 4
        for (int ss = 0; ss < 16; ++ss) {
            const uint4 ahi = *(const uint4*)(pa + ss * 256);
            const uint4 alo = *(const uint4*)(pa + ss * 256 + HA_LO_OFF);
            const uint4 b0h = *(const uint4*)(pb0 + ss * 256);
            const uint4 b0l = *(const uint4*)(pb0 + ss * 256 + WB_LO_OFF);
            const uint4 b1h = *(const uint4*)(pb1 + ss * 256);
            const uint4 b1l = *(const uint4*)(pb1 + ss * 256 + WB_LO_OFF);
            mma_bf16(d00, ahi, b0h.x, b0h.y);
            mma_bf16(d01, ahi, b0h.z, b0h.w);
            mma_bf16(d10, ahi, b1h.x, b1h.y);
            mma_bf16(d11, ahi, b1h.z, b1h.w);
            mma_bf16(d00, ahi, b0l.x, b0l.y);
            mma_bf16(d01, ahi, b0l.z, b0l.w);
            mma_bf16(d10, ahi, b1l.x, b1l.y);
            mma_bf16(d11, ahi, b1l.z, b1l.w);
            mma_bf16(d00, alo, b0h.x, b0h.y);
            mma_bf16(d01, alo, b0h.z, b0h.w);
            mma_bf16(d10, alo, b1h.x, b1h.y);
            mma_bf16(d11, alo, b1h.z, b1h.w);
        }

        // store partials: tile j at cols 16*(2*colg+j); rows g2, g2+8; cols 2*t4
        {
            const int g2 = lane >> 2, t4 = lane & 3;
            float* rd0 = &redD[ksub][0][16 * (2 * colg)];
            *(float2*)&rd0[g2 * 128 + 2 * t4]           = make_float2(d00.x, d00.y);
            *(float2*)&rd0[(g2 + 8) * 128 + 2 * t4]     = make_float2(d00.z, d00.w);
            *(float2*)&rd0[g2 * 128 + 8 + 2 * t4]       = make_float2(d01.x, d01.y);
            *(float2*)&rd0[(g2 + 8) * 128 + 8 + 2 * t4] = make_float2(d01.z, d01.w);
            float* rd1 = rd0 + 16;
            *(float2*)&rd1[g2 * 128 + 2 * t4]           = make_float2(d10.x, d10.y);
            *(float2*)&rd1[(g2 + 8) * 128 + 2 * t4]     = make_float2(d10.z, d10.w);
            *(float2*)&rd1[g2 * 128 + 8 + 2 * t4]       = make_float2(d11.x, d11.y);
            *(float2*)&rd1[(g2 + 8) * 128 + 8 + 2 * t4] = make_float2(d11.z, d11.w);
        }
        __syncthreads();

        // reduce 4 ksub partials + xh + tanh + dual-format store
#pragma unroll
        for (int v = 0; v < 2; ++v) {
            const int rr = rr_v[v];
            const int c = c_v[v];
            const float2 p0 = *(const float2*)&redD[0][rr][c];
            const float2 p1 = *(const float2*)&redD[1][rr][c];
            const float2 p2 = *(const float2*)&redD[2][rr][c];
            const float2 p3 = *(const float2*)&redD[3][rr][c];
            const float sx = (p0.x + p1.x) + (p2.x + p3.x);
            const float sy = (p0.y + p1.y) + (p2.y + p3.y);
            write_h_pair(tanhf(xh_pre[v].x + sx), tanhf(xh_pre[v].y + sy),
                         16 * gidx + rr, c & 15, 8 * rank + (c >> 4), t, y);
        }

        // publish h_t to cluster peers; HW barrier (also covers redD reuse)
        __threadfence();
        asm volatile("barrier.cluster.arrive.aligned;\n" ::: "memory");
        asm volatile("barrier.cluster.wait.aligned;\n" ::: "memory");
    }
}

// ---------------------------------------------------------------------------
// Kernel A: xh = x @ W_xh + (b_xh + b_hh).  fp32 SGEMM (proven correct).
// ---------------------------------------------------------------------------
__global__ __launch_bounds__(256, 2)
void gemm_xh_kernel(const float* __restrict__ A, const float* __restrict__ B,
                    const float* __restrict__ bxh, const float* __restrict__ bhh)
{
    __shared__ float As[8][128];
    __shared__ float Bs[8][128];

    const int tid = threadIdx.x;
    const int bm = blockIdx.y * 128;
    const int bn = blockIdx.x * 128;
    const int tx = tid & 15;
    const int ty = tid >> 4;

    const int a_row = tid >> 1;
    const int a_col = (tid & 1) << 2;
    const int b_row = tid >> 5;
    const int b_col = (tid & 31) << 2;

    const float* Aptr = A + (size_t)(bm + a_row) * DD + a_col;
    const float* Bptr = B + (size_t)b_row * HH + bn + b_col;

    float acc[8][8];
#pragma unroll
    for (int i = 0; i < 8; ++i)
#pragma unroll
        for (int j = 0; j < 8; ++j) acc[i][j] = 0.0f;

    for (int k0 = 0; k0 < DD; k0 += 8) {
        const float4 av = *(const float4*)(Aptr + k0);
        const float4 bv = *(const float4*)(Bptr + (size_t)k0 * HH);
        As[a_col + 0][a_row] = av.x;
        As[a_col + 1][a_row] = av.y;
        As[a_col + 2][a_row] = av.z;
        As[a_col + 3][a_row] = av.w;
        *(float4*)&Bs[b_row][b_col] = bv;
        __syncthreads();

#pragma unroll
        for (int k = 0; k < 8; ++k) {
            float a_frag[8], b_frag[8];
            *(float4*)&a_frag[0] = *(const float4*)&As[k][ty * 8];
            *(float4*)&a_frag[4] = *(const float4*)&As[k][ty * 8 + 4];
            *(float4*)&b_frag[0] = *(const float4*)&Bs[k][tx * 8];
            *(float4*)&b_frag[4] = *(const float4*)&Bs[k][tx * 8 + 4];
#pragma unroll
            for (int i = 0; i < 8; ++i)
#pragma unroll
                for (int j = 0; j < 8; ++j)
                    acc[i][j] = fmaf(a_frag[i], b_frag[j], acc[i][j]);
        }
        __syncthreads();
    }

    float bsum[8];
#pragma unroll
    for (int j = 0; j < 8; ++j) {
        const int col = bn + tx * 8 + j;
        bsum[j] = bxh[col] + bhh[col];
    }
#pragma unroll
    for (int i = 0; i < 8; ++i) {
        float* Crow = g_xh + (size_t)(bm + ty * 8 + i) * HH + bn + tx * 8;
        float4 o0, o1;
        o0.x = acc[i][0] + bsum[0]; o0.y = acc[i][1] + bsum[1];
        o0.z = acc[i][2] + bsum[2]; o0.w = acc[i][3] + bsum[3];
        o1.x = acc[i][4] + bsum[4]; o1.y = acc[i][5] + bsum[5];
        o1.z = acc[i][6] + bsum[6]; o1.w = acc[i][7] + bsum[7];
        *(float4*)(Crow + 0) = o0;
        *(float4*)(Crow + 4) = o1;
    }
}

// ---------------------------------------------------------------------------
// Launch. Inputs: x, weight_xh, weight_hh, bias_xh, bias_hh.
// Pure kernel launches, static smem only, HW cluster barriers only.
// ---------------------------------------------------------------------------
extern "C" void kernel_launch(void* const* d_in, const int* in_sizes, int n_in,
                              void* d_out, int out_size)
{
    const float* x   = (const float*)d_in[0];
    const float* wxh = (const float*)d_in[1];
    const float* whh = (const float*)d_in[2];
    const float* bxh = (const float*)d_in[3];
    const float* bhh = (const float*)d_in[4];
    float* y = (float*)d_out;

    (void)in_sizes; (void)n_in; (void)out_size;

    split_w_kernel<<<4096, 256>>>(whh);

    dim3 g1(HH / 128, (NB * TT) / 128);   // (8, 256)
    gemm_xh_kernel<<<g1, 256>>>(x, wxh, bxh, bhh);

    rnn_persistent_cluster<<<32, 512>>>(y);
}